// round 14
// baseline (speedup 1.0000x reference)
#include <cuda_runtime.h>
#include <cuda_bf16.h>
#include <math.h>
#include <stdint.h>

// Problem dims
#define Bsz 64
#define Tt  250
#define Dd  768
#define Hh  12
#define Ll  12
#define Ff  32
#define DHd 64
#define Mm  (Bsz*Tt)            // 16000 rows
#define KA  1536                // compact split activations [Ah | Al]
#define K2  2304                // weight K: [Wh ; Wh ; Wl]
#define NQKV 1536               // fused [Qf'(384) | Kf'(384) | V(768)]
#define VS  768                 // v-only f32 row stride
#define BK  64
#define NCHUNK (K2/BK)          // 36
#define ROWB 144                // padded SMEM row stride (bytes) for 128B of data
#define ATILE (128*ROWB)        // 18432
#define STAGE (2*ATILE)         // 36864 (A+B)
#define HG_SMEM (2*STAGE)       // 73728 (2-stage, 2 CTAs/SM)

// ---------------- scratch (static device globals; no allocation) -------------
__device__ float g_x  [Mm*Dd];
__device__ float g_v  [(size_t)Mm*VS];
__device__ float g_tmp[Mm*Dd];            // O / FF2 output (residual input)
__device__ float g_Qf[Mm*Hh*Ff];
__device__ float g_Kf[Mm*Hh*Ff];
__device__ float g_Z [Mm*Hh];
__device__ int   g_len[Bsz];
__device__ float g_bqkv[Ll*NQKV];
// bf16 compact split activation buffers [Mm, KA]
__device__ __nv_bfloat16 g_a2x[(size_t)Mm*KA];
__device__ __nv_bfloat16 g_a2o[(size_t)Mm*KA];
__device__ __nv_bfloat16 g_a2y[(size_t)Mm*KA];
// bf16 split transposed weights: qkv packed [L, 1536(n), K2], others [L, 768(n), K2]
__device__ __nv_bfloat16 g_Wtqkv[(size_t)Ll*NQKV*K2];
__device__ __nv_bfloat16 g_Wto[(size_t)Ll*Dd*K2];
__device__ __nv_bfloat16 g_Wt1[(size_t)Ll*Dd*K2];
__device__ __nv_bfloat16 g_Wt2[(size_t)Ll*Dd*K2];

// ---------------- small helpers ----------------------------------------------
__device__ __forceinline__ float gelu_exact(float v) {
    return 0.5f * v * (1.0f + erff(v * 0.70710678118654752f));
}
__device__ __forceinline__ void split_bf16(float v, __nv_bfloat16& hi, __nv_bfloat16& lo) {
    hi = __float2bfloat16(v);
    lo = __float2bfloat16(v - __bfloat162float(hi));
}
__device__ __forceinline__ void cp16(uint32_t saddr, const void* g) {
    asm volatile("cp.async.cg.shared.global [%0], [%1], 16;" :: "r"(saddr), "l"(g));
}
__device__ __forceinline__ void mma_bf16(float* d, const uint32_t* a, uint32_t b0, uint32_t b1) {
    asm volatile("mma.sync.aligned.m16n8k16.row.col.f32.bf16.bf16.f32 "
        "{%0,%1,%2,%3}, {%4,%5,%6,%7}, {%8,%9}, {%0,%1,%2,%3};"
        : "+f"(d[0]), "+f"(d[1]), "+f"(d[2]), "+f"(d[3])
        : "r"(a[0]), "r"(a[1]), "r"(a[2]), "r"(a[3]), "r"(b0), "r"(b1));
}

// ---- merged QKV weight prep: z<12 -> composite Q/K (layer z); z>=12 -> V -----
// qk part: W'[k, h*32+f] = sum_d W[k, h*64+d] * omega[d,f]; n = qk*384+h*32+f.
// v part:  straight transpose+split into n_off 768.
__global__ __launch_bounds__(256) void convall_kernel(
    const float* __restrict__ Wq, const float* __restrict__ Wk,
    const float* __restrict__ Wv, const float* __restrict__ omega,
    __nv_bfloat16* __restrict__ Wt)
{
    const int tid = threadIdx.x;
    if (blockIdx.z < Ll) {
        __shared__ float om[DHd][Ff];
        __shared__ float wt[32][DHd];
        const int l = blockIdx.z;
        const int k0 = blockIdx.x * 32;
        const int hq = blockIdx.y;        // 0..23
        const int qk = hq & 1, h = hq >> 1;
        const float* W = qk ? Wk : Wq;

        for (int i = tid; i < DHd*Ff; i += 256) om[i >> 5][i & 31] = omega[(size_t)l*DHd*Ff + i];
        for (int i = tid; i < 32*DHd; i += 256) {
            int kr = i >> 6, d = i & 63;
            wt[kr][d] = W[((size_t)l*Dd + k0 + kr)*Dd + h*DHd + d];
        }
        __syncthreads();
        #pragma unroll
        for (int it = 0; it < 4; it++) {
            int idx = tid + it*256;
            int kr = idx >> 5, f = idx & 31;
            float acc = 0.f;
            #pragma unroll 16
            for (int d = 0; d < DHd; d++)
                acc = fmaf(wt[kr][d], om[d][f], acc);
            __nv_bfloat16 hi, lo; split_bf16(acc, hi, lo);
            int n = qk*384 + h*Ff + f;
            size_t o = ((size_t)l*NQKV + n)*K2 + k0 + kr;
            Wt[o]        = hi;
            Wt[o + 768]  = hi;
            Wt[o + 1536] = lo;
        }
    } else {
        __shared__ float t[32][33];
        const int l = blockIdx.z - Ll, k0 = blockIdx.y*32, n0 = blockIdx.x*32;
        const int tx = tid & 31, ty = tid >> 5;
        for (int r = ty; r < 32; r += 8)
            t[r][tx] = Wv[(size_t)l*Dd*Dd + (size_t)(k0 + r)*Dd + n0 + tx];
        __syncthreads();
        for (int r = ty; r < 32; r += 8) {
            float w = t[tx][r];
            __nv_bfloat16 hi, lo; split_bf16(w, hi, lo);
            size_t o = ((size_t)l*NQKV + 768 + n0 + r)*K2 + k0 + tx;
            Wt[o]        = hi;
            Wt[o + 768]  = hi;
            Wt[o + 1536] = lo;
        }
    }
}

// ---- single-W convert: W[L,768k,768n] f32 -> Wt[L,768n,K2] bf16 --------------
__global__ __launch_bounds__(256) void convw_kernel(
    const float* __restrict__ W, __nv_bfloat16* __restrict__ Wt)
{
    __shared__ float t[32][33];
    const int l = blockIdx.z, k0 = blockIdx.y*32, n0 = blockIdx.x*32;
    const int tx = threadIdx.x & 31, ty = threadIdx.x >> 5;
    for (int r = ty; r < 32; r += 8)
        t[r][tx] = W[(size_t)l*Dd*Dd + (size_t)(k0 + r)*Dd + n0 + tx];
    __syncthreads();
    for (int r = ty; r < 32; r += 8) {
        float w = t[tx][r];
        __nv_bfloat16 hi, lo; split_bf16(w, hi, lo);
        size_t o = ((size_t)l*Dd + n0 + r)*K2 + k0 + tx;
        Wt[o]        = hi;
        Wt[o + 768]  = hi;
        Wt[o + 1536] = lo;
    }
}

// ---- prep: composite qkv bias (bq@om | bk@om | bv) + lengths from mask -------
__global__ void prep_kernel(const float* __restrict__ bq, const float* __restrict__ bk,
                            const float* __restrict__ bv, const float* __restrict__ omega,
                            float* __restrict__ bqkv,
                            const void* __restrict__ maskp, int* __restrict__ len) {
    const int blk = blockIdx.x;
    if (blk < Ll*6) {
        int l = blk / 6, part = blk - l*6;
        int col = part*256 + threadIdx.x; // 0..1535
        float v;
        if (col < 768) {
            int qk = col / 384, hf = col - qk*384;
            int h = hf >> 5, f = hf & 31;
            const float* bb = qk ? bk : bq;
            float acc = 0.f;
            for (int d = 0; d < DHd; d++)
                acc = fmaf(bb[l*Dd + h*DHd + d], omega[(size_t)l*DHd*Ff + d*Ff + f], acc);
            v = acc;
        } else {
            v = bv[l*Dd + col - 768];
        }
        bqkv[l*NQKV + col] = v;
        return;
    }
    // lengths (dtype-agnostic mask decode). Invariant: mask[:,0] == True.
    __shared__ int s_u8flag;
    __shared__ int s_cls;   // 0=uint8, 1=int32, 2=float32, 3=bf16
    const unsigned char* mb = (const unsigned char*)maskp;
    if (threadIdx.x == 0) {
        s_u8flag = 0;
        unsigned char b0 = mb[0], b2 = mb[2];
        if (b0 == 0x80u)      s_cls = 3;
        else if (b2 == 0x80u) s_cls = 2;
        else                  s_cls = 1;
    }
    __syncthreads();
    if (s_cls == 1) {
        int found = 0;
        for (int i = threadIdx.x; i < Bsz*Tt; i += blockDim.x)
            if ((i & 3) != 0 && mb[i] != 0) found = 1;
        if (found) atomicOr(&s_u8flag, 1);
    }
    __syncthreads();
    int cls = s_cls;
    if (cls == 1 && s_u8flag) cls = 0;
    int b = threadIdx.x;
    if (b < Bsz) {
        int s = 0;
        for (int t = 0; t < Tt; t++) {
            int i = b*Tt + t;
            bool m;
            if (cls == 0)      m = (mb[i] != 0);
            else if (cls == 1) m = (((const int*)maskp)[i] != 0);
            else if (cls == 2) m = (((const float*)maskp)[i] != 0.0f);
            else               m = ((((const unsigned short*)maskp)[i] & 0x7fffu) != 0);
            s += m ? 1 : 0;
        }
        len[b] = s;
    }
}

// ------------- embedding, 2 elems/thread (also writes split-bf16 A2) ----------
__global__ void embed_kernel(const int* __restrict__ batch, const float* __restrict__ tok,
                             const float* __restrict__ pos, float* __restrict__ x,
                             __nv_bfloat16* __restrict__ a2) {
    int gid = blockIdx.x * 256 + threadIdx.x;          // 0 .. Mm*Dd/2-1
    if (gid < Mm*(Dd/2)) {
        int m = gid / (Dd/2), dp = gid - m*(Dd/2);
        int d = dp * 2;
        int t = m % Tt;
        const float2 tv = *(const float2*)(tok + (size_t)batch[m]*Dd + d);
        const float2 pv = *(const float2*)(pos + (size_t)t*Dd + d);
        float2 v; v.x = tv.x + pv.x; v.y = tv.y + pv.y;
        *(float2*)(x + (size_t)m*Dd + d) = v;
        __nv_bfloat16 h0, l0, h1, l1;
        split_bf16(v.x, h0, l0); split_bf16(v.y, h1, l1);
        __nv_bfloat162 hh; hh.x = h0; hh.y = h1;
        __nv_bfloat162 ll; ll.x = l0; ll.y = l1;
        size_t o = (size_t)m*KA + d;
        *(__nv_bfloat162*)(a2 + o)       = hh;
        *(__nv_bfloat162*)(a2 + o + 768) = ll;
    }
}

// ---------------- HMMA bf16 GEMM: C[M,N] = A2[M,KA→K2 remap] @ Wt^T -----------
// 128x128 tile, 8 warps (2x4, each 64x32), BK=64, 2-stage cp.async, 2 CTAs/SM.
// Single __syncthreads per chunk (barrier also protects prefetch buffer).
// mode 0: C = f32(acc + bias), row stride Cstride.
// mode 1: gelu(acc+bias) -> A2out compact split-bf16 (stride KA).
// mode 2: fused QKV epilogue: cols 0..383 -> Qf=relu(acc+bias);
//         384..767 -> Kf=relu(acc+bias)*keymask; 768..1535 -> v (f32, stride VS).
__device__ __forceinline__ void ld_chunk(const __nv_bfloat16* Ab, const __nv_bfloat16* Bb,
                                         uint32_t sbase, int tid, int c, int buf)
{
    const uint32_t aoff = sbase + buf*STAGE;
    const uint32_t boff = aoff + ATILE;
    const int ak = (c < 24 ? c : c - 24) * BK;
    const int bk = c * BK;
    #pragma unroll
    for (int rr = 0; rr < 4; rr++) {
        int idx = tid + rr*256;              // 0..1023
        int row = idx >> 3, cc = idx & 7;    // row 0..127, 16B chunk 0..7
        uint32_t so = row*ROWB + cc*16;
        cp16(aoff + so, Ab + (size_t)row*KA + ak + cc*8);
        cp16(boff + so, Bb + (size_t)row*K2 + bk + cc*8);
    }
    asm volatile("cp.async.commit_group;" ::: "memory");
}

__global__ __launch_bounds__(256, 2) void hgemm(
    const __nv_bfloat16* __restrict__ A2, const __nv_bfloat16* __restrict__ Bt,
    const float* __restrict__ bias, float* __restrict__ C, int Cstride,
    __nv_bfloat16* __restrict__ A2out,
    float* __restrict__ Qf, float* __restrict__ Kf, const int* __restrict__ len,
    int mode)
{
    extern __shared__ char smem[];
    uint32_t sbase;
    asm("{ .reg .u64 t; cvta.to.shared.u64 t, %1; cvt.u32.u64 %0, t; }" : "=r"(sbase) : "l"(smem));
    const int tid = threadIdx.x, wid = tid >> 5, lane = tid & 31;
    const int bn = blockIdx.x, bm = blockIdx.y;
    const int wm = wid & 1, wn = wid >> 1;       // warp tile: rows wm*64, cols wn*32

    const __nv_bfloat16* Ab = A2 + (size_t)(bm*128)*KA;
    const __nv_bfloat16* Bb = Bt + (size_t)(bn*128)*K2;

    float acc[4][4][4];
    #pragma unroll
    for (int i = 0; i < 4; i++)
        #pragma unroll
        for (int j = 0; j < 4; j++)
            #pragma unroll
            for (int r = 0; r < 4; r++) acc[i][j][r] = 0.f;

    ld_chunk(Ab, Bb, sbase, tid, 0, 0);

    const int lrow = lane & 15, lhi = lane >> 4;              // A ldmatrix addressing
    const int nr = (lane & 7) + ((lane >> 4) << 3);           // B ldmatrix addressing
    const int kb = (lane >> 3) & 1;

    #pragma unroll 1
    for (int c = 0; c < NCHUNK; c++) {
        const int buf = c & 1;
        asm volatile("cp.async.wait_group 0;" ::: "memory");
        __syncthreads();
        if (c + 1 < NCHUNK)
            ld_chunk(Ab, Bb, sbase, tid, c + 1, buf ^ 1);

        const uint32_t abase = sbase + buf*STAGE + (wm*64)*ROWB;
        const uint32_t bbase = sbase + buf*STAGE + ATILE + (wn*32)*ROWB;
        #pragma unroll
        for (int ks = 0; ks < 4; ks++) {                      // four k16 steps
            uint32_t af[4][4], bf[2][4];
            #pragma unroll
            for (int i = 0; i < 4; i++) {
                uint32_t addr = abase + (i*16 + lrow)*ROWB + ks*32 + lhi*16;
                asm volatile("ldmatrix.sync.aligned.m8n8.x4.shared.b16 {%0,%1,%2,%3}, [%4];"
                    : "=r"(af[i][0]), "=r"(af[i][1]), "=r"(af[i][2]), "=r"(af[i][3]) : "r"(addr));
            }
            #pragma unroll
            for (int j = 0; j < 2; j++) {
                uint32_t addr = bbase + (j*16 + nr)*ROWB + ks*32 + kb*16;
                asm volatile("ldmatrix.sync.aligned.m8n8.x4.shared.b16 {%0,%1,%2,%3}, [%4];"
                    : "=r"(bf[j][0]), "=r"(bf[j][1]), "=r"(bf[j][2]), "=r"(bf[j][3]) : "r"(addr));
            }
            #pragma unroll
            for (int i = 0; i < 4; i++)
                #pragma unroll
                for (int jj = 0; jj < 4; jj++)
                    mma_bf16(acc[i][jj], af[i], bf[jj>>1][(jj&1)*2], bf[jj>>1][(jj&1)*2 + 1]);
        }
    }

    // ---- epilogue ----
    const int r0 = bm*128 + wm*64;
    const int c0 = bn*128 + wn*32;
    const int trow = lane >> 2, tcol = (lane & 3) * 2;
    int region = 0;            // mode 2: 0: Qf, 1: Kf, 2: v (uniform per warp)
    if (mode == 2) region = (c0 < 384) ? 0 : (c0 < 768 ? 1 : 2);

    #pragma unroll
    for (int i = 0; i < 4; i++) {
        #pragma unroll
        for (int half = 0; half < 2; half++) {
            const int row = r0 + i*16 + half*8 + trow;
            if (mode == 0) {
                float* Cr = C + (size_t)row*Cstride;
                #pragma unroll
                for (int jj = 0; jj < 4; jj++) {
                    int col = c0 + jj*8 + tcol;
                    float2 v;
                    v.x = acc[i][jj][half*2+0] + bias[col];
                    v.y = acc[i][jj][half*2+1] + bias[col+1];
                    *(float2*)(Cr + col) = v;
                }
            } else if (mode == 1) {
                __nv_bfloat16* Ao = A2out + (size_t)row*KA;
                #pragma unroll
                for (int jj = 0; jj < 4; jj++) {
                    int col = c0 + jj*8 + tcol;
                    float v0 = gelu_exact(acc[i][jj][half*2+0] + bias[col]);
                    float v1 = gelu_exact(acc[i][jj][half*2+1] + bias[col+1]);
                    __nv_bfloat16 h0, l0, h1, l1;
                    split_bf16(v0, h0, l0); split_bf16(v1, h1, l1);
                    __nv_bfloat162 hh; hh.x = h0; hh.y = h1;
                    __nv_bfloat162 ll; ll.x = l0; ll.y = l1;
                    *(__nv_bfloat162*)(Ao + col)       = hh;
                    *(__nv_bfloat162*)(Ao + 768 + col) = ll;
                }
            } else {
                if (region == 2) {
                    float* Cr = C + (size_t)row*VS - 768;
                    #pragma unroll
                    for (int jj = 0; jj < 4; jj++) {
                        int col = c0 + jj*8 + tcol;
                        float2 v;
                        v.x = acc[i][jj][half*2+0] + bias[col];
                        v.y = acc[i][jj][half*2+1] + bias[col+1];
                        *(float2*)(Cr + col) = v;
                    }
                } else {
                    float keep = 1.f;
                    if (region == 1) {
                        int b = row / Tt, t = row - b*Tt;
                        keep = (t < len[b]) ? 1.f : 0.f;
                    }
                    float* dst = (region ? Kf : Qf) + (size_t)row*(Hh*Ff) - region*384;
                    #pragma unroll
                    for (int jj = 0; jj < 4; jj++) {
                        int col = c0 + jj*8 + tcol;
                        float2 v;
                        v.x = fmaxf(acc[i][jj][half*2+0] + bias[col], 0.f) * keep;
                        v.y = fmaxf(acc[i][jj][half*2+1] + bias[col+1], 0.f) * keep;
                        *(float2*)(dst + col) = v;
                    }
                }
            }
        }
    }
}

// --- fused KV+Z+out: per (b,h): KV = Kf^T V (smem), then out = Z*(Qf@KV) ------
// writes out directly as compact split-bf16 a2o; saves Z.
__global__ __launch_bounds__(256) void kvz_kernel(
    const float* __restrict__ Kf, const float* __restrict__ vsrc,
    const float* __restrict__ Qf, __nv_bfloat16* __restrict__ a2o,
    float* __restrict__ Z)
{
    const int bh = blockIdx.x;
    const int b = bh / Hh, h = bh - b*Hh;
    __shared__ float kfs[4][Ff];
    __shared__ float vs [4][DHd];
    __shared__ float kvs[Ff][DHd];     // 8KB
    __shared__ float kss[Ff];
    __shared__ float qfs[4][Ff];
    const int tid = threadIdx.x;
    const int f = tid & 31, mb = tid >> 5;
    float acc[8] = {0,0,0,0,0,0,0,0};
    float ks = 0.f;

    // phase 1: KV[f][m] = sum_s Kf[s,f] * v[s,m]
    for (int s0 = 0; s0 < Tt; s0 += 4) {
        {
            int si = tid >> 6, m = tid & 63;
            int s = s0 + si;
            vs[si][m] = (s < Tt) ? vsrc[(size_t)(b*Tt + s)*VS + h*DHd + m] : 0.f;
            if (tid < 128) {
                int si2 = tid >> 5, ff = tid & 31;
                int s2 = s0 + si2;
                kfs[si2][ff] = (s2 < Tt) ? Kf[(size_t)(b*Tt + s2)*(Hh*Ff) + h*Ff + ff] : 0.f;
            }
        }
        __syncthreads();
        #pragma unroll
        for (int si = 0; si < 4; si++) {
            float kv = kfs[si][f];
            if (mb == 0) ks += kv;
            #pragma unroll
            for (int j = 0; j < 8; j++)
                acc[j] = fmaf(kv, vs[si][mb*8 + j], acc[j]);
        }
        __syncthreads();
    }
    #pragma unroll
    for (int j = 0; j < 8; j++)
        kvs[f][mb*8 + j] = acc[j];
    if (mb == 0) kss[f] = ks;
    __syncthreads();

    // phase 2: out[t,m] = Z * sum_f Qf[t,f]*KV[f][m]
    const int tl = tid >> 6, m = tid & 63;
    for (int t0 = 0; t0 < Tt; t0 += 4) {
        if (tid < 128) {
            int ti = tid >> 5, ff = tid & 31;
            int t = t0 + ti;
            qfs[ti][ff] = (t < Tt) ? Qf[(size_t)(b*Tt + t)*(Hh*Ff) + h*Ff + ff] : 0.f;
        }
        __syncthreads();
        int t = t0 + tl;
        if (t < Tt) {
            float zden = 1e-6f, o = 0.f;
            #pragma unroll
            for (int ff = 0; ff < Ff; ff++) {
                float qv = qfs[tl][ff];
                zden = fmaf(qv, kss[ff], zden);
                o    = fmaf(qv, kvs[ff][m], o);
            }
            float z = 1.f / zden;
            float val = o * z;
            __nv_bfloat16 hi, lo; split_bf16(val, hi, lo);
            size_t base = (size_t)(b*Tt + t)*KA + h*DHd + m;
            a2o[base] = hi; a2o[base + 768] = lo;
            if (m == 0) Z[(size_t)(b*Tt + t)*Hh + h] = z;
        }
        __syncthreads();
    }
}

// -------- residual add + LayerNorm (in place on x, + compact split A2) -------
__global__ __launch_bounds__(256) void addln_kernel(
    float* __restrict__ x, const float* __restrict__ r,
    const float* __restrict__ g, const float* __restrict__ bb,
    __nv_bfloat16* __restrict__ a2)
{
    const int m = blockIdx.x;
    const int tid = threadIdx.x;
    const size_t base = (size_t)m * Dd;
    float v0 = x[base + tid      ] + r[base + tid      ];
    float v1 = x[base + tid + 256] + r[base + tid + 256];
    float v2 = x[base + tid + 512] + r[base + tid + 512];
    float s  = v0 + v1 + v2;
    float s2 = v0*v0 + v1*v1 + v2*v2;
    #pragma unroll
    for (int o = 16; o; o >>= 1) {
        s  += __shfl_down_sync(0xffffffffu, s,  o);
        s2 += __shfl_down_sync(0xffffffffu, s2, o);
    }
    __shared__ float red[2][8];
    __shared__ float mv[2];
    int lane = tid & 31, w = tid >> 5;
    if (!lane) { red[0][w] = s; red[1][w] = s2; }
    __syncthreads();
    if (tid == 0) {
        float a = 0.f, c = 0.f;
        #pragma unroll
        for (int i = 0; i < 8; i++) { a += red[0][i]; c += red[1][i]; }
        float mean = a * (1.f/768.f);
        mv[0] = mean;
        mv[1] = rsqrtf(c * (1.f/768.f) - mean*mean + 1e-5f);
    }
    __syncthreads();
    float mean = mv[0], inv = mv[1];
    const size_t b2o = (size_t)m * KA;
    #pragma unroll
    for (int jj = 0; jj < 3; jj++) {
        int col = tid + jj*256;
        float vv = (jj == 0 ? v0 : (jj == 1 ? v1 : v2));
        float o = (vv - mean) * inv * g[col] + bb[col];
        x[base + col] = o;
        __nv_bfloat16 hi, lo; split_bf16(o, hi, lo);
        a2[b2o + col] = hi; a2[b2o + 768 + col] = lo;
    }
}

// ---------------- attn[b,h,t,s] = Z[b,t,h] * sum_f Qf*Kf ---------------------
__global__ __launch_bounds__(256) void attn_kernel(
    const float* __restrict__ Qf, const float* __restrict__ Kf,
    const float* __restrict__ Z, float* __restrict__ attn)
{
    const int bh = blockIdx.y;
    const int b = bh / Hh, h = bh - b*Hh;
    const int t0 = blockIdx.x * 32;
    __shared__ float Qs[32][33];
    __shared__ float Ks[64][33];
    __shared__ float zs[32];
    const int tid = threadIdx.x;

    for (int i = tid; i < 32*32; i += 256) {
        int tl = i >> 5, f = i & 31;
        int t = t0 + tl;
        Qs[tl][f] = (t < Tt) ? Qf[(size_t)(b*Tt + t)*(Hh*Ff) + h*Ff + f] : 0.f;
    }
    if (tid < 32) {
        int t = t0 + tid;
        zs[tid] = (t < Tt) ? Z[(size_t)(b*Tt + t)*Hh + h] : 0.f;
    }
    __syncthreads();

    const int sl = tid & 63, tg = tid >> 6;
    for (int s0 = 0; s0 < Tt; s0 += 64) {
        for (int i = tid; i < 64*32; i += 256) {
            int si = i >> 5, f = i & 31;
            int s = s0 + si;
            Ks[si][f] = (s < Tt) ? Kf[(size_t)(b*Tt + s)*(Hh*Ff) + h*Ff + f] : 0.f;
        }
        __syncthreads();
        int s = s0 + sl;
        #pragma unroll
        for (int ii = 0; ii < 8; ii++) {
            int tl = tg + ii*4;
            int t = t0 + tl;
            if (t < Tt && s < Tt) {
                float d = 0.f;
                #pragma unroll
                for (int f = 0; f < Ff; f++)
                    d = fmaf(Qs[tl][f], Ks[sl][f], d);
                attn[((size_t)bh*Tt + t)*Tt + s] = d * zs[tl];
            }
        }
        __syncthreads();
    }
}

// ---------------- CLS gather -------------------------------------------------
__global__ void cls_kernel(const float* __restrict__ x, float* __restrict__ out) {
    int idx = blockIdx.x * 256 + threadIdx.x;
    if (idx < Bsz*Dd) {
        int b = idx / Dd, d = idx - b*Dd;
        out[idx] = x[(size_t)(b*Tt)*Dd + d];
    }
}

// ---------------- launch -----------------------------------------------------
extern "C" void kernel_launch(void* const* d_in, const int* in_sizes, int n_in,
                              void* d_out, int out_size) {
    (void)in_sizes; (void)n_in; (void)out_size;
    const int*   batch = (const int*)  d_in[0];
    const void*  mask  = d_in[1];
    const float* tok   = (const float*)d_in[2];
    const float* pos   = (const float*)d_in[3];
    const float* Wq    = (const float*)d_in[4];
    const float* bq    = (const float*)d_in[5];
    const float* Wk    = (const float*)d_in[6];
    const float* bk    = (const float*)d_in[7];
    const float* Wv    = (const float*)d_in[8];
    const float* bv    = (const float*)d_in[9];
    const float* Wo    = (const float*)d_in[10];
    const float* bo    = (const float*)d_in[11];
    const float* omega = (const float*)d_in[12];
    const float* ln1g  = (const float*)d_in[13];
    const float* ln1b  = (const float*)d_in[14];
    const float* ln2g  = (const float*)d_in[15];
    const float* ln2b  = (const float*)d_in[16];
    const float* W1    = (const float*)d_in[17];
    const float* b1    = (const float*)d_in[18];
    const float* W2    = (const float*)d_in[19];
    const float* b2    = (const float*)d_in[20];
    float* out = (float*)d_out;

    float *x,*v,*tmp,*Qf,*Kf,*Z,*bqkv; int* len;
    __nv_bfloat16 *a2x,*a2o,*a2y,*Wtqkv,*Wto,*Wt1,*Wt2;
    cudaGetSymbolAddress((void**)&x,    g_x);
    cudaGetSymbolAddress((void**)&v,    g_v);
    cudaGetSymbolAddress((void**)&tmp,  g_tmp);
    cudaGetSymbolAddress((void**)&Qf,   g_Qf);
    cudaGetSymbolAddress((void**)&Kf,   g_Kf);
    cudaGetSymbolAddress((void**)&Z,    g_Z);
    cudaGetSymbolAddress((void**)&bqkv, g_bqkv);
    cudaGetSymbolAddress((void**)&len,  g_len);
    cudaGetSymbolAddress((void**)&a2x,  g_a2x);
    cudaGetSymbolAddress((void**)&a2o,  g_a2o);
    cudaGetSymbolAddress((void**)&a2y,  g_a2y);
    cudaGetSymbolAddress((void**)&Wtqkv,g_Wtqkv);
    cudaGetSymbolAddress((void**)&Wto,  g_Wto);
    cudaGetSymbolAddress((void**)&Wt1,  g_Wt1);
    cudaGetSymbolAddress((void**)&Wt2,  g_Wt2);

    static bool attr_set = false;
    if (!attr_set) {
        cudaFuncSetAttribute(hgemm, cudaFuncAttributeMaxDynamicSharedMemorySize, HG_SMEM);
        attr_set = true;
    }

    // launch order: convall(0), prep(1), embed(2), hgemm(3) — profiler slot 3
    convall_kernel<<<dim3(24, 24, 24), 256>>>(Wq, Wk, Wv, omega, Wtqkv);
    prep_kernel<<<Ll*6 + 1, 256>>>(bq, bk, bv, omega, bqkv, mask, len);
    embed_kernel<<<(Mm*(Dd/2) + 255)/256, 256>>>(batch, tok, pos, x, a2x);

    dim3 gqkv(NQKV/128, Mm/128);   // (12, 125)
    dim3 gg(Dd/128, Mm/128);       // (6, 125)
    dim3 cg(24, 24, 12);
    const size_t WTQ = (size_t)NQKV*K2;
    const size_t WT  = (size_t)Dd*K2;

    hgemm<<<gqkv, 256, HG_SMEM>>>(a2x, Wtqkv, bqkv, v, VS, nullptr, Qf, Kf, len, 2);  // idx 3

    convw_kernel<<<cg, 256>>>(Wo, Wto);
    convw_kernel<<<cg, 256>>>(W1, Wt1);
    convw_kernel<<<cg, 256>>>(W2, Wt2);

    for (int l = 0; l < Ll; l++) {
        const size_t BO = (size_t)l * Dd;
        if (l > 0)
            hgemm<<<gqkv, 256, HG_SMEM>>>(a2x, Wtqkv + l*WTQ, bqkv + l*NQKV, v, VS,
                                          nullptr, Qf, Kf, len, 2);
        kvz_kernel<<<Bsz*Hh, 256>>>(Kf, v, Qf, a2o, Z);
        hgemm<<<gg, 256, HG_SMEM>>>(a2o, Wto + l*WT, bo + BO, tmp, Dd,
                                    nullptr, nullptr, nullptr, nullptr, 0);
        addln_kernel<<<Mm, 256>>>(x, tmp, ln1g + BO, ln1b + BO, a2x);
        hgemm<<<gg, 256, HG_SMEM>>>(a2x, Wt1 + l*WT, b1 + BO, nullptr, 0,
                                    a2y, nullptr, nullptr, nullptr, 1);
        hgemm<<<gg, 256, HG_SMEM>>>(a2y, Wt2 + l*WT, b2 + BO, tmp, Dd,
                                    nullptr, nullptr, nullptr, nullptr, 0);
        addln_kernel<<<Mm, 256>>>(x, tmp, ln2g + BO, ln2b + BO, a2x);
    }
    attn_kernel<<<dim3((Tt + 31)/32, Bsz*Hh), 256>>>(Qf, Kf, Z, out + Bsz*Dd);
    cls_kernel<<<(Bsz*Dd + 255)/256, 256>>>(x, out);
}

// round 16
// speedup vs baseline: 1.0613x; 1.0613x over previous
#include <cuda_runtime.h>
#include <cuda_bf16.h>
#include <math.h>
#include <stdint.h>

// Problem dims
#define Bsz 64
#define Tt  250
#define Dd  768
#define Hh  12
#define Ll  12
#define Ff  32
#define DHd 64
#define Mm  (Bsz*Tt)            // 16000 rows
#define KA  1536                // compact split activations [Ah | Al]
#define K2  2304                // weight K: [Wh ; Wh ; Wl]
#define NQKV 1536               // fused [Qf'(384) | Kf'(384) | V(768)]
#define VS  768                 // v-only f32 row stride
#define BK  64
#define NCHUNK (K2/BK)          // 36
#define ROWB 144                // padded SMEM row stride (bytes) for 128B of data
#define ATILE (128*ROWB)        // 18432
#define STAGE (2*ATILE)         // 36864 (A+B)
#define HG_SMEM (2*STAGE)       // 73728 (2-stage, 2 CTAs/SM)

// ---------------- scratch (static device globals; no allocation) -------------
__device__ float g_x  [Mm*Dd];
__device__ float g_v  [(size_t)Mm*VS];
__device__ float g_tmp[Mm*Dd];            // O / FF2 output (residual input)
__device__ float g_Qf[Mm*Hh*Ff];
__device__ float g_Kf[Mm*Hh*Ff];
__device__ float g_KV[Bsz*Hh*Ff*DHd];
__device__ float g_Ks[Bsz*Hh*Ff];
__device__ float g_Z [Mm*Hh];
__device__ int   g_len[Bsz];
__device__ float g_bqkv[Ll*NQKV];
// bf16 compact split activation buffers [Mm, KA]
__device__ __nv_bfloat16 g_a2x[(size_t)Mm*KA];
__device__ __nv_bfloat16 g_a2o[(size_t)Mm*KA];
__device__ __nv_bfloat16 g_a2y[(size_t)Mm*KA];
// bf16 split transposed weights: qkv packed [L, 1536(n), K2], others [L, 768(n), K2]
__device__ __nv_bfloat16 g_Wtqkv[(size_t)Ll*NQKV*K2];
__device__ __nv_bfloat16 g_Wto[(size_t)Ll*Dd*K2];
__device__ __nv_bfloat16 g_Wt1[(size_t)Ll*Dd*K2];
__device__ __nv_bfloat16 g_Wt2[(size_t)Ll*Dd*K2];

// ---------------- small helpers ----------------------------------------------
__device__ __forceinline__ float gelu_exact(float v) {
    return 0.5f * v * (1.0f + erff(v * 0.70710678118654752f));
}
__device__ __forceinline__ void split_bf16(float v, __nv_bfloat16& hi, __nv_bfloat16& lo) {
    hi = __float2bfloat16(v);
    lo = __float2bfloat16(v - __bfloat162float(hi));
}
__device__ __forceinline__ void cp16(uint32_t saddr, const void* g) {
    asm volatile("cp.async.cg.shared.global [%0], [%1], 16;" :: "r"(saddr), "l"(g));
}
__device__ __forceinline__ void mma_bf16(float* d, const uint32_t* a, uint32_t b0, uint32_t b1) {
    asm volatile("mma.sync.aligned.m16n8k16.row.col.f32.bf16.bf16.f32 "
        "{%0,%1,%2,%3}, {%4,%5,%6,%7}, {%8,%9}, {%0,%1,%2,%3};"
        : "+f"(d[0]), "+f"(d[1]), "+f"(d[2]), "+f"(d[3])
        : "r"(a[0]), "r"(a[1]), "r"(a[2]), "r"(a[3]), "r"(b0), "r"(b1));
}

// ---- merged QKV weight prep: z<12 -> composite Q/K (layer z); z>=12 -> V -----
__global__ __launch_bounds__(256) void convall_kernel(
    const float* __restrict__ Wq, const float* __restrict__ Wk,
    const float* __restrict__ Wv, const float* __restrict__ omega,
    __nv_bfloat16* __restrict__ Wt)
{
    const int tid = threadIdx.x;
    if (blockIdx.z < Ll) {
        __shared__ float om[DHd][Ff];
        __shared__ float wt[32][DHd];
        const int l = blockIdx.z;
        const int k0 = blockIdx.x * 32;
        const int hq = blockIdx.y;        // 0..23
        const int qk = hq & 1, h = hq >> 1;
        const float* W = qk ? Wk : Wq;

        for (int i = tid; i < DHd*Ff; i += 256) om[i >> 5][i & 31] = omega[(size_t)l*DHd*Ff + i];
        for (int i = tid; i < 32*DHd; i += 256) {
            int kr = i >> 6, d = i & 63;
            wt[kr][d] = W[((size_t)l*Dd + k0 + kr)*Dd + h*DHd + d];
        }
        __syncthreads();
        #pragma unroll
        for (int it = 0; it < 4; it++) {
            int idx = tid + it*256;
            int kr = idx >> 5, f = idx & 31;
            float acc = 0.f;
            #pragma unroll 16
            for (int d = 0; d < DHd; d++)
                acc = fmaf(wt[kr][d], om[d][f], acc);
            __nv_bfloat16 hi, lo; split_bf16(acc, hi, lo);
            int n = qk*384 + h*Ff + f;
            size_t o = ((size_t)l*NQKV + n)*K2 + k0 + kr;
            Wt[o]        = hi;
            Wt[o + 768]  = hi;
            Wt[o + 1536] = lo;
        }
    } else {
        __shared__ float t[32][33];
        const int l = blockIdx.z - Ll, k0 = blockIdx.y*32, n0 = blockIdx.x*32;
        const int tx = tid & 31, ty = tid >> 5;
        for (int r = ty; r < 32; r += 8)
            t[r][tx] = Wv[(size_t)l*Dd*Dd + (size_t)(k0 + r)*Dd + n0 + tx];
        __syncthreads();
        for (int r = ty; r < 32; r += 8) {
            float w = t[tx][r];
            __nv_bfloat16 hi, lo; split_bf16(w, hi, lo);
            size_t o = ((size_t)l*NQKV + 768 + n0 + r)*K2 + k0 + tx;
            Wt[o]        = hi;
            Wt[o + 768]  = hi;
            Wt[o + 1536] = lo;
        }
    }
}

// ---- single-W convert: W[L,768k,768n] f32 -> Wt[L,768n,K2] bf16 --------------
__global__ __launch_bounds__(256) void convw_kernel(
    const float* __restrict__ W, __nv_bfloat16* __restrict__ Wt)
{
    __shared__ float t[32][33];
    const int l = blockIdx.z, k0 = blockIdx.y*32, n0 = blockIdx.x*32;
    const int tx = threadIdx.x & 31, ty = threadIdx.x >> 5;
    for (int r = ty; r < 32; r += 8)
        t[r][tx] = W[(size_t)l*Dd*Dd + (size_t)(k0 + r)*Dd + n0 + tx];
    __syncthreads();
    for (int r = ty; r < 32; r += 8) {
        float w = t[tx][r];
        __nv_bfloat16 hi, lo; split_bf16(w, hi, lo);
        size_t o = ((size_t)l*Dd + n0 + r)*K2 + k0 + tx;
        Wt[o]        = hi;
        Wt[o + 768]  = hi;
        Wt[o + 1536] = lo;
    }
}

// ---- prep: composite qkv bias (bq@om | bk@om | bv) + lengths from mask -------
__global__ void prep_kernel(const float* __restrict__ bq, const float* __restrict__ bk,
                            const float* __restrict__ bv, const float* __restrict__ omega,
                            float* __restrict__ bqkv,
                            const void* __restrict__ maskp, int* __restrict__ len) {
    const int blk = blockIdx.x;
    if (blk < Ll*6) {
        int l = blk / 6, part = blk - l*6;
        int col = part*256 + threadIdx.x; // 0..1535
        float v;
        if (col < 768) {
            int qk = col / 384, hf = col - qk*384;
            int h = hf >> 5, f = hf & 31;
            const float* bb = qk ? bk : bq;
            float acc = 0.f;
            for (int d = 0; d < DHd; d++)
                acc = fmaf(bb[l*Dd + h*DHd + d], omega[(size_t)l*DHd*Ff + d*Ff + f], acc);
            v = acc;
        } else {
            v = bv[l*Dd + col - 768];
        }
        bqkv[l*NQKV + col] = v;
        return;
    }
    // lengths (dtype-agnostic mask decode). Invariant: mask[:,0] == True.
    __shared__ int s_u8flag;
    __shared__ int s_cls;   // 0=uint8, 1=int32, 2=float32, 3=bf16
    const unsigned char* mb = (const unsigned char*)maskp;
    if (threadIdx.x == 0) {
        s_u8flag = 0;
        unsigned char b0 = mb[0], b2 = mb[2];
        if (b0 == 0x80u)      s_cls = 3;
        else if (b2 == 0x80u) s_cls = 2;
        else                  s_cls = 1;
    }
    __syncthreads();
    if (s_cls == 1) {
        int found = 0;
        for (int i = threadIdx.x; i < Bsz*Tt; i += blockDim.x)
            if ((i & 3) != 0 && mb[i] != 0) found = 1;
        if (found) atomicOr(&s_u8flag, 1);
    }
    __syncthreads();
    int cls = s_cls;
    if (cls == 1 && s_u8flag) cls = 0;
    int b = threadIdx.x;
    if (b < Bsz) {
        int s = 0;
        for (int t = 0; t < Tt; t++) {
            int i = b*Tt + t;
            bool m;
            if (cls == 0)      m = (mb[i] != 0);
            else if (cls == 1) m = (((const int*)maskp)[i] != 0);
            else if (cls == 2) m = (((const float*)maskp)[i] != 0.0f);
            else               m = ((((const unsigned short*)maskp)[i] & 0x7fffu) != 0);
            s += m ? 1 : 0;
        }
        len[b] = s;
    }
}

// ------------- embedding, 2 elems/thread (also writes split-bf16 A2) ----------
__global__ void embed_kernel(const int* __restrict__ batch, const float* __restrict__ tok,
                             const float* __restrict__ pos, float* __restrict__ x,
                             __nv_bfloat16* __restrict__ a2) {
    int gid = blockIdx.x * 256 + threadIdx.x;          // 0 .. Mm*Dd/2-1
    if (gid < Mm*(Dd/2)) {
        int m = gid / (Dd/2), dp = gid - m*(Dd/2);
        int d = dp * 2;
        int t = m % Tt;
        const float2 tv = *(const float2*)(tok + (size_t)batch[m]*Dd + d);
        const float2 pv = *(const float2*)(pos + (size_t)t*Dd + d);
        float2 v; v.x = tv.x + pv.x; v.y = tv.y + pv.y;
        *(float2*)(x + (size_t)m*Dd + d) = v;
        __nv_bfloat16 h0, l0, h1, l1;
        split_bf16(v.x, h0, l0); split_bf16(v.y, h1, l1);
        __nv_bfloat162 hh; hh.x = h0; hh.y = h1;
        __nv_bfloat162 ll; ll.x = l0; ll.y = l1;
        size_t o = (size_t)m*KA + d;
        *(__nv_bfloat162*)(a2 + o)       = hh;
        *(__nv_bfloat162*)(a2 + o + 768) = ll;
    }
}

// ---------------- HMMA bf16 GEMM: C[M,N] = A2[M,KA→K2 remap] @ Wt^T -----------
// 128x128 tile, 8 warps (2x4, each 64x32), BK=64, 2-stage cp.async, 2 CTAs/SM.
// Single __syncthreads per chunk (barrier also protects prefetch buffer).
// mode 0: C = f32(acc + bias), row stride Cstride.
// mode 1: gelu(acc+bias) -> A2out compact split-bf16 (stride KA).
// mode 2: fused QKV epilogue: cols 0..383 -> Qf=relu(acc+bias);
//         384..767 -> Kf=relu(acc+bias)*keymask; 768..1535 -> v (f32, stride VS).
__device__ __forceinline__ void ld_chunk(const __nv_bfloat16* Ab, const __nv_bfloat16* Bb,
                                         uint32_t sbase, int tid, int c, int buf)
{
    const uint32_t aoff = sbase + buf*STAGE;
    const uint32_t boff = aoff + ATILE;
    const int ak = (c < 24 ? c : c - 24) * BK;
    const int bk = c * BK;
    #pragma unroll
    for (int rr = 0; rr < 4; rr++) {
        int idx = tid + rr*256;              // 0..1023
        int row = idx >> 3, cc = idx & 7;    // row 0..127, 16B chunk 0..7
        uint32_t so = row*ROWB + cc*16;
        cp16(aoff + so, Ab + (size_t)row*KA + ak + cc*8);
        cp16(boff + so, Bb + (size_t)row*K2 + bk + cc*8);
    }
    asm volatile("cp.async.commit_group;" ::: "memory");
}

__global__ __launch_bounds__(256, 2) void hgemm(
    const __nv_bfloat16* __restrict__ A2, const __nv_bfloat16* __restrict__ Bt,
    const float* __restrict__ bias, float* __restrict__ C, int Cstride,
    __nv_bfloat16* __restrict__ A2out,
    float* __restrict__ Qf, float* __restrict__ Kf, const int* __restrict__ len,
    int mode)
{
    extern __shared__ char smem[];
    uint32_t sbase;
    asm("{ .reg .u64 t; cvta.to.shared.u64 t, %1; cvt.u32.u64 %0, t; }" : "=r"(sbase) : "l"(smem));
    const int tid = threadIdx.x, wid = tid >> 5, lane = tid & 31;
    const int bn = blockIdx.x, bm = blockIdx.y;
    const int wm = wid & 1, wn = wid >> 1;       // warp tile: rows wm*64, cols wn*32

    const __nv_bfloat16* Ab = A2 + (size_t)(bm*128)*KA;
    const __nv_bfloat16* Bb = Bt + (size_t)(bn*128)*K2;

    float acc[4][4][4];
    #pragma unroll
    for (int i = 0; i < 4; i++)
        #pragma unroll
        for (int j = 0; j < 4; j++)
            #pragma unroll
            for (int r = 0; r < 4; r++) acc[i][j][r] = 0.f;

    ld_chunk(Ab, Bb, sbase, tid, 0, 0);

    const int lrow = lane & 15, lhi = lane >> 4;              // A ldmatrix addressing
    const int nr = (lane & 7) + ((lane >> 4) << 3);           // B ldmatrix addressing
    const int kb = (lane >> 3) & 1;

    #pragma unroll 1
    for (int c = 0; c < NCHUNK; c++) {
        const int buf = c & 1;
        asm volatile("cp.async.wait_group 0;" ::: "memory");
        __syncthreads();
        if (c + 1 < NCHUNK)
            ld_chunk(Ab, Bb, sbase, tid, c + 1, buf ^ 1);

        const uint32_t abase = sbase + buf*STAGE + (wm*64)*ROWB;
        const uint32_t bbase = sbase + buf*STAGE + ATILE + (wn*32)*ROWB;
        #pragma unroll
        for (int ks = 0; ks < 4; ks++) {                      // four k16 steps
            uint32_t af[4][4], bf[2][4];
            #pragma unroll
            for (int i = 0; i < 4; i++) {
                uint32_t addr = abase + (i*16 + lrow)*ROWB + ks*32 + lhi*16;
                asm volatile("ldmatrix.sync.aligned.m8n8.x4.shared.b16 {%0,%1,%2,%3}, [%4];"
                    : "=r"(af[i][0]), "=r"(af[i][1]), "=r"(af[i][2]), "=r"(af[i][3]) : "r"(addr));
            }
            #pragma unroll
            for (int j = 0; j < 2; j++) {
                uint32_t addr = bbase + (j*16 + nr)*ROWB + ks*32 + kb*16;
                asm volatile("ldmatrix.sync.aligned.m8n8.x4.shared.b16 {%0,%1,%2,%3}, [%4];"
                    : "=r"(bf[j][0]), "=r"(bf[j][1]), "=r"(bf[j][2]), "=r"(bf[j][3]) : "r"(addr));
            }
            #pragma unroll
            for (int i = 0; i < 4; i++)
                #pragma unroll
                for (int jj = 0; jj < 4; jj++)
                    mma_bf16(acc[i][jj], af[i], bf[jj>>1][(jj&1)*2], bf[jj>>1][(jj&1)*2 + 1]);
        }
    }

    // ---- epilogue ----
    const int r0 = bm*128 + wm*64;
    const int c0 = bn*128 + wn*32;
    const int trow = lane >> 2, tcol = (lane & 3) * 2;
    int region = 0;            // mode 2: 0: Qf, 1: Kf, 2: v (uniform per warp)
    if (mode == 2) region = (c0 < 384) ? 0 : (c0 < 768 ? 1 : 2);

    #pragma unroll
    for (int i = 0; i < 4; i++) {
        #pragma unroll
        for (int half = 0; half < 2; half++) {
            const int row = r0 + i*16 + half*8 + trow;
            if (mode == 0) {
                float* Cr = C + (size_t)row*Cstride;
                #pragma unroll
                for (int jj = 0; jj < 4; jj++) {
                    int col = c0 + jj*8 + tcol;
                    float2 v;
                    v.x = acc[i][jj][half*2+0] + bias[col];
                    v.y = acc[i][jj][half*2+1] + bias[col+1];
                    *(float2*)(Cr + col) = v;
                }
            } else if (mode == 1) {
                __nv_bfloat16* Ao = A2out + (size_t)row*KA;
                #pragma unroll
                for (int jj = 0; jj < 4; jj++) {
                    int col = c0 + jj*8 + tcol;
                    float v0 = gelu_exact(acc[i][jj][half*2+0] + bias[col]);
                    float v1 = gelu_exact(acc[i][jj][half*2+1] + bias[col+1]);
                    __nv_bfloat16 h0, l0, h1, l1;
                    split_bf16(v0, h0, l0); split_bf16(v1, h1, l1);
                    __nv_bfloat162 hh; hh.x = h0; hh.y = h1;
                    __nv_bfloat162 ll; ll.x = l0; ll.y = l1;
                    *(__nv_bfloat162*)(Ao + col)       = hh;
                    *(__nv_bfloat162*)(Ao + 768 + col) = ll;
                }
            } else {
                if (region == 2) {
                    float* Cr = C + (size_t)row*VS - 768;
                    #pragma unroll
                    for (int jj = 0; jj < 4; jj++) {
                        int col = c0 + jj*8 + tcol;
                        float2 v;
                        v.x = acc[i][jj][half*2+0] + bias[col];
                        v.y = acc[i][jj][half*2+1] + bias[col+1];
                        *(float2*)(Cr + col) = v;
                    }
                } else {
                    float keep = 1.f;
                    if (region == 1) {
                        int b = row / Tt, t = row - b*Tt;
                        keep = (t < len[b]) ? 1.f : 0.f;
                    }
                    float* dst = (region ? Kf : Qf) + (size_t)row*(Hh*Ff) - region*384;
                    #pragma unroll
                    for (int jj = 0; jj < 4; jj++) {
                        int col = c0 + jj*8 + tcol;
                        float2 v;
                        v.x = fmaxf(acc[i][jj][half*2+0] + bias[col], 0.f) * keep;
                        v.y = fmaxf(acc[i][jj][half*2+1] + bias[col+1], 0.f) * keep;
                        *(float2*)(dst + col) = v;
                    }
                }
            }
        }
    }
}

// ---------------- KV[b,h,f,m] = sum_s Kf[b,s,h,f]*v[b,s,h,m];  Ksum ----------
__global__ __launch_bounds__(256) void kv_kernel(
    const float* __restrict__ Kf, const float* __restrict__ vsrc,
    float* __restrict__ KV, float* __restrict__ Ksum)
{
    const int bh = blockIdx.x;
    const int b = bh / Hh, h = bh - b*Hh;
    __shared__ float kfs[4][Ff];
    __shared__ float vs [4][DHd];
    const int tid = threadIdx.x;
    const int f = tid & 31, mb = tid >> 5;
    float acc[8] = {0,0,0,0,0,0,0,0};
    float ks = 0.f;

    for (int s0 = 0; s0 < Tt; s0 += 4) {
        {
            int si = tid >> 6, m = tid & 63;
            int s = s0 + si;
            vs[si][m] = (s < Tt) ? vsrc[(size_t)(b*Tt + s)*VS + h*DHd + m] : 0.f;
            if (tid < 128) {
                int si2 = tid >> 5, ff = tid & 31;
                int s2 = s0 + si2;
                kfs[si2][ff] = (s2 < Tt) ? Kf[(size_t)(b*Tt + s2)*(Hh*Ff) + h*Ff + ff] : 0.f;
            }
        }
        __syncthreads();
        #pragma unroll
        for (int si = 0; si < 4; si++) {
            float kv = kfs[si][f];
            if (mb == 0) ks += kv;
            #pragma unroll
            for (int j = 0; j < 8; j++)
                acc[j] = fmaf(kv, vs[si][mb*8 + j], acc[j]);
        }
        __syncthreads();
    }
    #pragma unroll
    for (int j = 0; j < 8; j++)
        KV[((size_t)bh*Ff + f)*DHd + mb*8 + j] = acc[j];
    if (mb == 0) Ksum[(size_t)bh*Ff + f] = ks;
}

// ---- out = Z * (Qf @ KV) written directly as compact split-bf16 A2; Z saved --
__global__ __launch_bounds__(256) void zout_kernel(
    const float* __restrict__ Qf, const float* __restrict__ KV,
    const float* __restrict__ Ksum, __nv_bfloat16* __restrict__ a2o,
    float* __restrict__ Z)
{
    const int bh = blockIdx.x;
    const int b = bh / Hh, h = bh - b*Hh;
    __shared__ float kvs[Ff][DHd];
    __shared__ float kss[Ff];
    __shared__ float qfs[4][Ff];
    const int tid = threadIdx.x;
    for (int i = tid; i < Ff*DHd; i += 256) kvs[i >> 6][i & 63] = KV[(size_t)bh*Ff*DHd + i];
    if (tid < Ff) kss[tid] = Ksum[(size_t)bh*Ff + tid];
    __syncthreads();

    const int tl = tid >> 6, m = tid & 63;
    for (int t0 = 0; t0 < Tt; t0 += 4) {
        if (tid < 128) {
            int ti = tid >> 5, f = tid & 31;
            int t = t0 + ti;
            qfs[ti][f] = (t < Tt) ? Qf[(size_t)(b*Tt + t)*(Hh*Ff) + h*Ff + f] : 0.f;
        }
        __syncthreads();
        int t = t0 + tl;
        if (t < Tt) {
            float zden = 1e-6f, o = 0.f;
            #pragma unroll
            for (int f = 0; f < Ff; f++) {
                float qv = qfs[tl][f];
                zden = fmaf(qv, kss[f], zden);
                o    = fmaf(qv, kvs[f][m], o);
            }
            float z = 1.f / zden;
            float val = o * z;
            __nv_bfloat16 hi, lo; split_bf16(val, hi, lo);
            size_t base = (size_t)(b*Tt + t)*KA + h*DHd + m;
            a2o[base] = hi; a2o[base + 768] = lo;
            if (m == 0) Z[(size_t)(b*Tt + t)*Hh + h] = z;
        }
        __syncthreads();
    }
}

// -------- residual add + LayerNorm (in place on x, + compact split A2) -------
__global__ __launch_bounds__(256) void addln_kernel(
    float* __restrict__ x, const float* __restrict__ r,
    const float* __restrict__ g, const float* __restrict__ bb,
    __nv_bfloat16* __restrict__ a2)
{
    const int m = blockIdx.x;
    const int tid = threadIdx.x;
    const size_t base = (size_t)m * Dd;
    float v0 = x[base + tid      ] + r[base + tid      ];
    float v1 = x[base + tid + 256] + r[base + tid + 256];
    float v2 = x[base + tid + 512] + r[base + tid + 512];
    float s  = v0 + v1 + v2;
    float s2 = v0*v0 + v1*v1 + v2*v2;
    #pragma unroll
    for (int o = 16; o; o >>= 1) {
        s  += __shfl_down_sync(0xffffffffu, s,  o);
        s2 += __shfl_down_sync(0xffffffffu, s2, o);
    }
    __shared__ float red[2][8];
    __shared__ float mv[2];
    int lane = tid & 31, w = tid >> 5;
    if (!lane) { red[0][w] = s; red[1][w] = s2; }
    __syncthreads();
    if (tid == 0) {
        float a = 0.f, c = 0.f;
        #pragma unroll
        for (int i = 0; i < 8; i++) { a += red[0][i]; c += red[1][i]; }
        float mean = a * (1.f/768.f);
        mv[0] = mean;
        mv[1] = rsqrtf(c * (1.f/768.f) - mean*mean + 1e-5f);
    }
    __syncthreads();
    float mean = mv[0], inv = mv[1];
    const size_t b2o = (size_t)m * KA;
    #pragma unroll
    for (int jj = 0; jj < 3; jj++) {
        int col = tid + jj*256;
        float vv = (jj == 0 ? v0 : (jj == 1 ? v1 : v2));
        float o = (vv - mean) * inv * g[col] + bb[col];
        x[base + col] = o;
        __nv_bfloat16 hi, lo; split_bf16(o, hi, lo);
        a2[b2o + col] = hi; a2[b2o + 768 + col] = lo;
    }
}

// ---------------- attn[b,h,t,s] = Z[b,t,h] * sum_f Qf*Kf ---------------------
__global__ __launch_bounds__(256) void attn_kernel(
    const float* __restrict__ Qf, const float* __restrict__ Kf,
    const float* __restrict__ Z, float* __restrict__ attn)
{
    const int bh = blockIdx.y;
    const int b = bh / Hh, h = bh - b*Hh;
    const int t0 = blockIdx.x * 32;
    __shared__ float Qs[32][33];
    __shared__ float Ks[64][33];
    __shared__ float zs[32];
    const int tid = threadIdx.x;

    for (int i = tid; i < 32*32; i += 256) {
        int tl = i >> 5, f = i & 31;
        int t = t0 + tl;
        Qs[tl][f] = (t < Tt) ? Qf[(size_t)(b*Tt + t)*(Hh*Ff) + h*Ff + f] : 0.f;
    }
    if (tid < 32) {
        int t = t0 + tid;
        zs[tid] = (t < Tt) ? Z[(size_t)(b*Tt + t)*Hh + h] : 0.f;
    }
    __syncthreads();

    const int sl = tid & 63, tg = tid >> 6;
    for (int s0 = 0; s0 < Tt; s0 += 64) {
        for (int i = tid; i < 64*32; i += 256) {
            int si = i >> 5, f = i & 31;
            int s = s0 + si;
            Ks[si][f] = (s < Tt) ? Kf[(size_t)(b*Tt + s)*(Hh*Ff) + h*Ff + f] : 0.f;
        }
        __syncthreads();
        int s = s0 + sl;
        #pragma unroll
        for (int ii = 0; ii < 8; ii++) {
            int tl = tg + ii*4;
            int t = t0 + tl;
            if (t < Tt && s < Tt) {
                float d = 0.f;
                #pragma unroll
                for (int f = 0; f < Ff; f++)
                    d = fmaf(Qs[tl][f], Ks[sl][f], d);
                attn[((size_t)bh*Tt + t)*Tt + s] = d * zs[tl];
            }
        }
        __syncthreads();
    }
}

// ---------------- CLS gather -------------------------------------------------
__global__ void cls_kernel(const float* __restrict__ x, float* __restrict__ out) {
    int idx = blockIdx.x * 256 + threadIdx.x;
    if (idx < Bsz*Dd) {
        int b = idx / Dd, d = idx - b*Dd;
        out[idx] = x[(size_t)(b*Tt)*Dd + d];
    }
}

// ---------------- launch -----------------------------------------------------
extern "C" void kernel_launch(void* const* d_in, const int* in_sizes, int n_in,
                              void* d_out, int out_size) {
    (void)in_sizes; (void)n_in; (void)out_size;
    const int*   batch = (const int*)  d_in[0];
    const void*  mask  = d_in[1];
    const float* tok   = (const float*)d_in[2];
    const float* pos   = (const float*)d_in[3];
    const float* Wq    = (const float*)d_in[4];
    const float* bq    = (const float*)d_in[5];
    const float* Wk    = (const float*)d_in[6];
    const float* bk    = (const float*)d_in[7];
    const float* Wv    = (const float*)d_in[8];
    const float* bv    = (const float*)d_in[9];
    const float* Wo    = (const float*)d_in[10];
    const float* bo    = (const float*)d_in[11];
    const float* omega = (const float*)d_in[12];
    const float* ln1g  = (const float*)d_in[13];
    const float* ln1b  = (const float*)d_in[14];
    const float* ln2g  = (const float*)d_in[15];
    const float* ln2b  = (const float*)d_in[16];
    const float* W1    = (const float*)d_in[17];
    const float* b1    = (const float*)d_in[18];
    const float* W2    = (const float*)d_in[19];
    const float* b2    = (const float*)d_in[20];
    float* out = (float*)d_out;

    float *x,*v,*tmp,*Qf,*Kf,*KV,*Ks,*Z,*bqkv; int* len;
    __nv_bfloat16 *a2x,*a2o,*a2y,*Wtqkv,*Wto,*Wt1,*Wt2;
    cudaGetSymbolAddress((void**)&x,    g_x);
    cudaGetSymbolAddress((void**)&v,    g_v);
    cudaGetSymbolAddress((void**)&tmp,  g_tmp);
    cudaGetSymbolAddress((void**)&Qf,   g_Qf);
    cudaGetSymbolAddress((void**)&Kf,   g_Kf);
    cudaGetSymbolAddress((void**)&KV,   g_KV);
    cudaGetSymbolAddress((void**)&Ks,   g_Ks);
    cudaGetSymbolAddress((void**)&Z,    g_Z);
    cudaGetSymbolAddress((void**)&bqkv, g_bqkv);
    cudaGetSymbolAddress((void**)&len,  g_len);
    cudaGetSymbolAddress((void**)&a2x,  g_a2x);
    cudaGetSymbolAddress((void**)&a2o,  g_a2o);
    cudaGetSymbolAddress((void**)&a2y,  g_a2y);
    cudaGetSymbolAddress((void**)&Wtqkv,g_Wtqkv);
    cudaGetSymbolAddress((void**)&Wto,  g_Wto);
    cudaGetSymbolAddress((void**)&Wt1,  g_Wt1);
    cudaGetSymbolAddress((void**)&Wt2,  g_Wt2);

    static bool attr_set = false;
    if (!attr_set) {
        cudaFuncSetAttribute(hgemm, cudaFuncAttributeMaxDynamicSharedMemorySize, HG_SMEM);
        attr_set = true;
    }

    // launch order: convall(0), prep(1), embed(2), hgemm(3) — profiler slot 3
    convall_kernel<<<dim3(24, 24, 24), 256>>>(Wq, Wk, Wv, omega, Wtqkv);
    prep_kernel<<<Ll*6 + 1, 256>>>(bq, bk, bv, omega, bqkv, mask, len);
    embed_kernel<<<(Mm*(Dd/2) + 255)/256, 256>>>(batch, tok, pos, x, a2x);

    dim3 gqkv(NQKV/128, Mm/128);   // (12, 125)
    dim3 gg(Dd/128, Mm/128);       // (6, 125)
    dim3 cg(24, 24, 12);
    const size_t WTQ = (size_t)NQKV*K2;
    const size_t WT  = (size_t)Dd*K2;

    hgemm<<<gqkv, 256, HG_SMEM>>>(a2x, Wtqkv, bqkv, v, VS, nullptr, Qf, Kf, len, 2);  // idx 3

    convw_kernel<<<cg, 256>>>(Wo, Wto);
    convw_kernel<<<cg, 256>>>(W1, Wt1);
    convw_kernel<<<cg, 256>>>(W2, Wt2);

    for (int l = 0; l < Ll; l++) {
        const size_t BO = (size_t)l * Dd;
        if (l > 0)
            hgemm<<<gqkv, 256, HG_SMEM>>>(a2x, Wtqkv + l*WTQ, bqkv + l*NQKV, v, VS,
                                          nullptr, Qf, Kf, len, 2);
        kv_kernel  <<<Bsz*Hh, 256>>>(Kf, v, KV, Ks);
        zout_kernel<<<Bsz*Hh, 256>>>(Qf, KV, Ks, a2o, Z);
        hgemm<<<gg, 256, HG_SMEM>>>(a2o, Wto + l*WT, bo + BO, tmp, Dd,
                                    nullptr, nullptr, nullptr, nullptr, 0);
        addln_kernel<<<Mm, 256>>>(x, tmp, ln1g + BO, ln1b + BO, a2x);
        hgemm<<<gg, 256, HG_SMEM>>>(a2x, Wt1 + l*WT, b1 + BO, nullptr, 0,
                                    a2y, nullptr, nullptr, nullptr, 1);
        hgemm<<<gg, 256, HG_SMEM>>>(a2y, Wt2 + l*WT, b2 + BO, tmp, Dd,
                                    nullptr, nullptr, nullptr, nullptr, 0);
        addln_kernel<<<Mm, 256>>>(x, tmp, ln2g + BO, ln2b + BO, a2x);
    }
    attn_kernel<<<dim3((Tt + 31)/32, Bsz*Hh), 256>>>(Qf, Kf, Z, out + Bsz*Dd);
    cls_kernel<<<(Bsz*Dd + 255)/256, 256>>>(x, out);
}